// round 11
// baseline (speedup 1.0000x reference)
#include <cuda_runtime.h>
#include <cuda_fp16.h>
#include <math.h>
#include <stdint.h>

// Problem constants
#define BATCH 2
#define SEQ   2048
#define HID   1024
#define NH    16
#define HD    64
#define MROWS (BATCH * SEQ)   // 4096

// Q pre-scale: HD^-0.5 * log2(e)  (softmax done in exp2 domain)
#define QSCALE (0.125f * 1.44269504088896f)

// ---------------- scratch (static device globals; no runtime alloc) ----------
__device__ __half g_q[MROWS * HID];      // pre-scaled by QSCALE
__device__ __half g_k[MROWS * HID];      // [seq][hid]
__device__ __half g_vt[MROWS * HID];     // [(b*NH+h)*HD+d][seq]
__device__ __half g_att[MROWS * HID];    // [seq][hid]
__device__ __half g_hs[MROWS * HID];
__device__ __half g_wqkv[3 * HID * HID]; // rows: [wq; wk; wv]
__device__ __half g_wo[HID * HID];
__device__ float  g_bqkv[3 * HID];

// ============================================================================
// helpers
// ============================================================================
__device__ __forceinline__ void cp16(uint32_t s, const void* g) {
    asm volatile("cp.async.cg.shared.global [%0], [%1], 16;" :: "r"(s), "l"(g));
}
#define CP_COMMIT() asm volatile("cp.async.commit_group;" ::: "memory")
template <int N>
__device__ __forceinline__ void cp_wait() {
    asm volatile("cp.async.wait_group %0;" :: "n"(N) : "memory");
}
__device__ __forceinline__ uint32_t smem_u32(const void* p) {
    uint32_t a;
    asm("{ .reg .u64 t; cvta.to.shared.u64 t, %1; cvt.u32.u64 %0, t; }"
        : "=r"(a) : "l"(p));
    return a;
}
__device__ __forceinline__ void mma_f16(
    float& c0, float& c1, float& c2, float& c3,
    uint32_t a0, uint32_t a1, uint32_t a2, uint32_t a3,
    uint32_t b0, uint32_t b1)
{
    asm volatile(
        "mma.sync.aligned.m16n8k16.row.col.f32.f16.f16.f32 "
        "{%0,%1,%2,%3}, {%4,%5,%6,%7}, {%8,%9}, {%0,%1,%2,%3};"
        : "+f"(c0), "+f"(c1), "+f"(c2), "+f"(c3)
        : "r"(a0), "r"(a1), "r"(a2), "r"(a3), "r"(b0), "r"(b1));
}
__device__ __forceinline__ void ldsm4(
    uint32_t& r0, uint32_t& r1, uint32_t& r2, uint32_t& r3, uint32_t a)
{
    asm volatile("ldmatrix.sync.aligned.m8n8.x4.shared.b16 {%0,%1,%2,%3}, [%4];"
                 : "=r"(r0), "=r"(r1), "=r"(r2), "=r"(r3) : "r"(a));
}
__device__ __forceinline__ uint32_t pack_h2(float a, float b) {
    __half2 h = __floats2half2_rn(a, b);
    return *(uint32_t*)&h;
}
__device__ __forceinline__ float ex2(float x) {
    float y;
    asm("ex2.approx.f32 %0, %1;" : "=f"(y) : "f"(x));
    return y;
}

// ============================================================================
// conversion kernels
// ============================================================================
__global__ void conv_h(const float4* __restrict__ in, __half2* __restrict__ out) {
    int i = blockIdx.x * blockDim.x + threadIdx.x;
    float4 v = in[i];
    out[2 * i]     = __floats2half2_rn(v.x, v.y);
    out[2 * i + 1] = __floats2half2_rn(v.z, v.w);
}

__global__ void conv_w4(const float4* __restrict__ wq, const float4* __restrict__ wk,
                        const float4* __restrict__ wv, const float4* __restrict__ wo,
                        __half2* __restrict__ wqkv, __half2* __restrict__ woh)
{
    int i = blockIdx.x * blockDim.x + threadIdx.x;
    int seg = i >> 18;
    int off = i & 0x3FFFF;
    const float4* src = seg == 0 ? wq : seg == 1 ? wk : seg == 2 ? wv : wo;
    float4 v = src[off];
    __half2 h0 = __floats2half2_rn(v.x, v.y);
    __half2 h1 = __floats2half2_rn(v.z, v.w);
    if (seg < 3) { wqkv[2 * i] = h0; wqkv[2 * i + 1] = h1; }
    else         { woh[2 * off] = h0; woh[2 * off + 1] = h1; }
}

__global__ void conv_b(const float* __restrict__ bq, const float* __restrict__ bk,
                       const float* __restrict__ bv, float* __restrict__ dst)
{
    int i = blockIdx.x * blockDim.x + threadIdx.x;
    const float* s = i < 1024 ? bq : i < 2048 ? bk : bv;
    dst[i] = s[i & 1023];
}

// ============================================================================
// Persistent fp16 GEMM: BK=64, 3-stage ring, one barrier per stage,
// CTA loops over tiles (grid = 2 * num_SMs).
// MODE 0: out f32 = acc + bias (O-projection)
// MODE 3: fused QKV epilogue, segment by global column
// ============================================================================
#define TBM 128
#define TBN 128
#define TBK 64
#define KSTAGES (HID / TBK)     // 16
#define ASTR 72                 // halfs per smem row (144B)
#define MATH2 (128 * ASTR)      // 9216 halfs per matrix per stage
#define MATB2 (MATH2 * 2)       // 18432 bytes
#define GSTAGES 3
#define GEMM_SMEM (GSTAGES * 2 * MATB2)   // 110592

__device__ __forceinline__ void g_load_stage(
    uint32_t sbase, int slot,
    const __half* __restrict__ X, const __half* __restrict__ W,
    int m0, int n0, int k0, int t)
{
    uint32_t aB = sbase + (uint32_t)(slot * 2) * MATB2;
    uint32_t bB = aB + MATB2;
    #pragma unroll
    for (int i = 0; i < 4; ++i) {
        int cid = t + (i << 8);          // 0..1023
        int r = cid >> 3;                // row 0..127
        int c = cid & 7;                 // 16B chunk 0..7
        uint32_t off = (uint32_t)r * (ASTR * 2) + (uint32_t)c * 16;
        cp16(aB + off, X + (size_t)(m0 + r) * HID + k0 + (c << 3));
        cp16(bB + off, W + (size_t)(n0 + r) * HID + k0 + (c << 3));
    }
}

template <int MODE>
__global__ __launch_bounds__(256, 2) void gemm_h(
    const __half* __restrict__ X, const __half* __restrict__ W,
    const float* __restrict__ bias, void* __restrict__ outv,
    int ntiles, int gx)
{
    extern __shared__ __align__(16) __half hsm[];
    const uint32_t sbase = smem_u32(hsm);

    const int t    = threadIdx.x;
    const int wid  = t >> 5;
    const int lane = t & 31;
    const int wr   = (wid >> 2) << 6;
    const int wc   = (wid & 3) << 5;
    const int lr   = lane >> 2;
    const int lc   = lane & 3;

    const int i8 = lane & 7, j4 = lane >> 3;
    const uint32_t aRow = (uint32_t)(((j4 & 1) << 3) + i8);
    const uint32_t aKo  = (uint32_t)((j4 >> 1) << 3);
    const uint32_t bRow = (uint32_t)(((j4 >> 1) << 3) + i8);
    const uint32_t bKo  = (uint32_t)((j4 & 1) << 3);

    for (int tile = blockIdx.x; tile < ntiles; tile += gridDim.x) {
        const int m0 = (tile / gx) * TBM;
        const int n0 = (tile % gx) * TBN;

        float acc[4][4][4] = {};

        g_load_stage(sbase, 0, X, W, m0, n0, 0, t);
        CP_COMMIT();
        g_load_stage(sbase, 1, X, W, m0, n0, TBK, t);
        CP_COMMIT();

        int slot = 0;
        for (int s = 0; s < KSTAGES; ++s) {
            if (s + 1 < KSTAGES) cp_wait<1>(); else cp_wait<0>();
            __syncthreads();

            if (s + 2 < KSTAGES) {
                int nslot = slot + 2; if (nslot >= GSTAGES) nslot -= GSTAGES;
                g_load_stage(sbase, nslot, X, W, m0, n0, (s + 2) * TBK, t);
                CP_COMMIT();
            }

            const uint32_t aB = sbase + (uint32_t)(slot * 2) * MATB2;
            const uint32_t bB = aB + MATB2;

            #pragma unroll
            for (int kk = 0; kk < 4; ++kk) {
                const uint32_t ko = (uint32_t)(kk << 4);
                uint32_t af[4][4];
                #pragma unroll
                for (int mi = 0; mi < 4; ++mi)
                    ldsm4(af[mi][0], af[mi][1], af[mi][2], af[mi][3],
                          aB + (((uint32_t)(wr + (mi << 4)) + aRow) * ASTR + ko + aKo) * 2);
                uint32_t bf[4][2];
                #pragma unroll
                for (int p = 0; p < 2; ++p)
                    ldsm4(bf[2 * p][0], bf[2 * p][1], bf[2 * p + 1][0], bf[2 * p + 1][1],
                          bB + (((uint32_t)(wc + (p << 4)) + bRow) * ASTR + ko + bKo) * 2);
                #pragma unroll
                for (int mi = 0; mi < 4; ++mi)
                    #pragma unroll
                    for (int ni = 0; ni < 4; ++ni)
                        mma_f16(acc[mi][ni][0], acc[mi][ni][1],
                                acc[mi][ni][2], acc[mi][ni][3],
                                af[mi][0], af[mi][1], af[mi][2], af[mi][3],
                                bf[ni][0], bf[ni][1]);
            }

            if (++slot >= GSTAGES) slot = 0;
        }

        const int seg = n0 >> 10;

        #pragma unroll
        for (int mi = 0; mi < 4; ++mi) {
            #pragma unroll
            for (int ni = 0; ni < 4; ++ni) {
                const int row = m0 + wr + (mi << 4) + lr;
                const int col = n0 + wc + (ni << 3) + (lc << 1);
                float2 b01 = *(const float2*)&bias[col];
                float v00 = acc[mi][ni][0] + b01.x;
                float v01 = acc[mi][ni][1] + b01.y;
                float v10 = acc[mi][ni][2] + b01.x;
                float v11 = acc[mi][ni][3] + b01.y;
                if (MODE == 0) {
                    float* out = (float*)outv;
                    *(float2*)&out[(size_t)row * HID + col] = make_float2(v00, v01);
                    *(float2*)&out[(size_t)(row + 8) * HID + col] = make_float2(v10, v11);
                } else {
                    const int c = col & 1023;
                    if (seg == 0) {
                        *(uint32_t*)&g_q[(size_t)row * HID + c] =
                            pack_h2(QSCALE * v00, QSCALE * v01);
                        *(uint32_t*)&g_q[(size_t)(row + 8) * HID + c] =
                            pack_h2(QSCALE * v10, QSCALE * v11);
                    } else if (seg == 1) {
                        *(uint32_t*)&g_k[(size_t)row * HID + c] = pack_h2(v00, v01);
                        *(uint32_t*)&g_k[(size_t)(row + 8) * HID + c] = pack_h2(v10, v11);
                    } else {
                        const int b0i = row >> 11, s0 = row & 2047;
                        const int b1i = (row + 8) >> 11, s1 = (row + 8) & 2047;
                        const int h0 = c >> 6, d0 = c & 63;
                        const int h1 = (c + 1) >> 6, d1 = (c + 1) & 63;
                        g_vt[((size_t)(b0i * NH + h0) * HD + d0) * SEQ + s0] = __float2half(v00);
                        g_vt[((size_t)(b0i * NH + h1) * HD + d1) * SEQ + s0] = __float2half(v01);
                        g_vt[((size_t)(b1i * NH + h0) * HD + d0) * SEQ + s1] = __float2half(v10);
                        g_vt[((size_t)(b1i * NH + h1) * HD + d1) * SEQ + s1] = __float2half(v11);
                    }
                }
            }
        }
        __syncthreads();   // protect ring slots before next tile's prologue
    }
}

// ============================================================================
// Persistent flash attention: QT=64, 4 warps, 3 CTAs/SM, 3-stage KV ring,
// pipelined fragment loads. CTA loops over (b,h,q-tile) units.
// ============================================================================
#define QT    64
#define ATHR  128
#define KT    64
#define NKT   (SEQ / KT)            // 32
#define NUNITS (BATCH * NH * (SEQ / QT))  // 1024
#define HSTR  72                    // halfs per smem row (144B)
#define KSTG2 (KT * HSTR)           // 4608 halfs per stage
#define ASTAGES 3
#define VBASE2 (ASTAGES * KSTG2)    // 13824
#define PBASE2 (VBASE2 + ASTAGES * KSTG2)  // 27648
#define PWARP2 (16 * HSTR)          // 1152
#define ATT_SMEM_BYTES ((PBASE2 + 4 * PWARP2) * 2)  // 64512

__device__ __forceinline__ void a_load_kv(
    uint32_t sbase, int slot, int b, int h, int k0, int t)
{
    const uint32_t kB = sbase + (uint32_t)slot * (KSTG2 * 2);
    const uint32_t vB = sbase + (uint32_t)(VBASE2 + slot * KSTG2) * 2;
    #pragma unroll
    for (int i = 0; i < 4; ++i) {
        int cid = t + (i << 7);
        int r = cid >> 3;
        int c = cid & 7;
        cp16(kB + (uint32_t)r * (HSTR * 2) + (uint32_t)c * 16,
             g_k + (size_t)(b * SEQ + k0 + r) * HID + h * HD + (c << 3));
        cp16(vB + (uint32_t)r * (HSTR * 2) + (uint32_t)c * 16,
             g_vt + ((size_t)(b * NH + h) * HD + r) * SEQ + k0 + (c << 3));
    }
}

__global__ __launch_bounds__(ATHR, 3) void attn_mma()
{
    extern __shared__ __align__(16) __half hsm[];
    const uint32_t sbase = smem_u32(hsm);

    const int t    = threadIdx.x;
    const int wid  = t >> 5;
    const int lane = t & 31;
    const int lr   = lane >> 2;
    const int lc   = lane & 3;

    const int i8 = lane & 7, j4 = lane >> 3;
    const uint32_t aRow = (uint32_t)(((j4 & 1) << 3) + i8);
    const uint32_t aKo  = (uint32_t)((j4 >> 1) << 3);
    const uint32_t bRow = (uint32_t)(((j4 >> 1) << 3) + i8);
    const uint32_t bKo  = (uint32_t)((j4 & 1) << 3);

    const uint32_t pB = sbase + (uint32_t)(PBASE2 + wid * PWARP2) * 2;
    __half* sPw = hsm + PBASE2 + wid * PWARP2;

    for (int unit = blockIdx.x; unit < NUNITS; unit += gridDim.x) {
        const int b  = unit >> 9;             // unit / 512
        const int h  = (unit >> 5) & 15;      // (unit / 32) % 16
        const int q0 = (unit & 31) * QT;
        const int wq = wid << 4;

        uint32_t qf[4][4];
        {
            const __half* Qg = g_q + (size_t)(b * SEQ + q0 + wq) * HID + h * HD;
            #pragma unroll
            for (int ks = 0; ks < 4; ++ks) {
                const int ko = (ks << 4) + (lc << 1);
                qf[ks][0] = *(const uint32_t*)&Qg[(size_t)lr * HID + ko];
                qf[ks][1] = *(const uint32_t*)&Qg[(size_t)(lr + 8) * HID + ko];
                qf[ks][2] = *(const uint32_t*)&Qg[(size_t)lr * HID + ko + 8];
                qf[ks][3] = *(const uint32_t*)&Qg[(size_t)(lr + 8) * HID + ko + 8];
            }
        }

        float O[8][4] = {};
        float mrow[2] = {-1e30f, -1e30f};
        float lrow[2] = {0.f, 0.f};

        a_load_kv(sbase, 0, b, h, 0, t);
        CP_COMMIT();
        a_load_kv(sbase, 1, b, h, KT, t);
        CP_COMMIT();

        int slot = 0;
        for (int kt = 0; kt < NKT; ++kt) {
            if (kt + 1 < NKT) cp_wait<1>(); else cp_wait<0>();
            __syncthreads();

            if (kt + 2 < NKT) {
                int nslot = slot + 2; if (nslot >= ASTAGES) nslot -= ASTAGES;
                a_load_kv(sbase, nslot, b, h, (kt + 2) * KT, t);
                CP_COMMIT();
            }

            const uint32_t kB = sbase + (uint32_t)slot * (KSTG2 * 2);
            const uint32_t vB = sbase + (uint32_t)(VBASE2 + slot * KSTG2) * 2;

            // ---- S = Qs @ K^T, pipelined K-fragment loads ----
            float S[8][4] = {};
            {
                uint32_t kf0[4], kf1[4];
                ldsm4(kf0[0], kf0[1], kf0[2], kf0[3], kB + (bRow * HSTR + bKo) * 2);
                #pragma unroll
                for (int idx = 0; idx < 16; ++idx) {
                    const int ks = idx >> 2, p = idx & 3;
                    uint32_t* cur = (idx & 1) ? kf1 : kf0;
                    uint32_t* nxt = (idx & 1) ? kf0 : kf1;
                    if (idx < 15) {
                        const int nks = (idx + 1) >> 2, np = (idx + 1) & 3;
                        ldsm4(nxt[0], nxt[1], nxt[2], nxt[3],
                              kB + (((uint32_t)(np << 4) + bRow) * HSTR
                                    + (uint32_t)(nks << 4) + bKo) * 2);
                    }
                    mma_f16(S[2*p][0], S[2*p][1], S[2*p][2], S[2*p][3],
                            qf[ks][0], qf[ks][1], qf[ks][2], qf[ks][3],
                            cur[0], cur[1]);
                    mma_f16(S[2*p+1][0], S[2*p+1][1], S[2*p+1][2], S[2*p+1][3],
                            qf[ks][0], qf[ks][1], qf[ks][2], qf[ks][3],
                            cur[2], cur[3]);
                }
            }

            // ---- online softmax (exp2 domain) ----
            #pragma unroll
            for (int r = 0; r < 2; ++r) {
                const int e0 = r << 1, e1 = e0 + 1;
                float mt = -1e30f;
                #pragma unroll
                for (int nt = 0; nt < 8; ++nt)
                    mt = fmaxf(mt, fmaxf(S[nt][e0], S[nt][e1]));
                mt = fmaxf(mt, __shfl_xor_sync(0xffffffffu, mt, 1));
                mt = fmaxf(mt, __shfl_xor_sync(0xffffffffu, mt, 2));
                float mnew = fmaxf(mrow[r], mt);
                float corr = ex2(mrow[r] - mnew);
                float rs = 0.f;
                #pragma unroll
                for (int nt = 0; nt < 8; ++nt) {
                    float p0 = ex2(S[nt][e0] - mnew);
                    float p1 = ex2(S[nt][e1] - mnew);
                    S[nt][e0] = p0; S[nt][e1] = p1;
                    rs += p0 + p1;
                }
                rs += __shfl_xor_sync(0xffffffffu, rs, 1);
                rs += __shfl_xor_sync(0xffffffffu, rs, 2);
                lrow[r] = lrow[r] * corr + rs;
                mrow[r] = mnew;
                #pragma unroll
                for (int nt = 0; nt < 8; ++nt) {
                    O[nt][e0] *= corr;
                    O[nt][e1] *= corr;
                }
            }

            // ---- P -> per-warp smem ----
            #pragma unroll
            for (int nt = 0; nt < 8; ++nt) {
                const int col = (nt << 3) + (lc << 1);
                *(uint32_t*)&sPw[lr * HSTR + col]       = pack_h2(S[nt][0], S[nt][1]);
                *(uint32_t*)&sPw[(lr + 8) * HSTR + col] = pack_h2(S[nt][2], S[nt][3]);
            }
            __syncwarp();

            // ---- O += P @ V, pipelined P/V fragment loads ----
            {
                uint32_t af0[4], af1[4], vf0[4], vf1[4];
                ldsm4(af0[0], af0[1], af0[2], af0[3], pB + (aRow * HSTR + aKo) * 2);
                ldsm4(vf0[0], vf0[1], vf0[2], vf0[3], vB + (bRow * HSTR + bKo) * 2);
                #pragma unroll
                for (int idx = 0; idx < 16; ++idx) {
                    const int ks = idx >> 2, p = idx & 3;
                    uint32_t* cura = (ks & 1) ? af1 : af0;
                    uint32_t* nxta = (ks & 1) ? af0 : af1;
                    uint32_t* curv = (idx & 1) ? vf1 : vf0;
                    uint32_t* nxtv = (idx & 1) ? vf0 : vf1;
                    if (p == 0 && ks < 3)
                        ldsm4(nxta[0], nxta[1], nxta[2], nxta[3],
                              pB + (aRow * HSTR + (uint32_t)((ks + 1) << 4) + aKo) * 2);
                    if (idx < 15) {
                        const int nks = (idx + 1) >> 2, np = (idx + 1) & 3;
                        ldsm4(nxtv[0], nxtv[1], nxtv[2], nxtv[3],
                              vB + (((uint32_t)(np << 4) + bRow) * HSTR
                                    + (uint32_t)(nks << 4) + bKo) * 2);
                    }
                    mma_f16(O[2*p][0], O[2*p][1], O[2*p][2], O[2*p][3],
                            cura[0], cura[1], cura[2], cura[3], curv[0], curv[1]);
                    mma_f16(O[2*p+1][0], O[2*p+1][1], O[2*p+1][2], O[2*p+1][3],
                            cura[0], cura[1], cura[2], cura[3], curv[2], curv[3]);
                }
            }

            if (++slot >= ASTAGES) slot = 0;
        }

        // ---- normalize + store half ----
        const float inv0 = 1.f / lrow[0];
        const float inv1 = 1.f / lrow[1];
        __half* Og = g_att + (size_t)(b * SEQ + q0 + wq) * HID + h * HD;
        #pragma unroll
        for (int nt = 0; nt < 8; ++nt) {
            const int col = (nt << 3) + (lc << 1);
            *(uint32_t*)&Og[(size_t)lr * HID + col] =
                pack_h2(O[nt][0] * inv0, O[nt][1] * inv0);
            *(uint32_t*)&Og[(size_t)(lr + 8) * HID + col] =
                pack_h2(O[nt][2] * inv1, O[nt][3] * inv1);
        }
        __syncthreads();   // protect KV ring before next unit's prologue
    }
}

// ---------------- launch ----------------------------------------------------
extern "C" void kernel_launch(void* const* d_in, const int* in_sizes, int n_in,
                              void* d_out, int out_size)
{
    const float* hs = (const float*)d_in[0];
    const float* wq = (const float*)d_in[1];
    const float* bq = (const float*)d_in[2];
    const float* wk = (const float*)d_in[3];
    const float* bk = (const float*)d_in[4];
    const float* wv = (const float*)d_in[5];
    const float* bv = (const float*)d_in[6];
    const float* wo = (const float*)d_in[7];
    const float* bo = (const float*)d_in[8];
    float* out = (float*)d_out;

    __half *hp, *wqkvp, *wop, *ap;
    float *bqkvp;
    cudaGetSymbolAddress((void**)&hp, g_hs);
    cudaGetSymbolAddress((void**)&wqkvp, g_wqkv);
    cudaGetSymbolAddress((void**)&wop, g_wo);
    cudaGetSymbolAddress((void**)&ap, g_att);
    cudaGetSymbolAddress((void**)&bqkvp, g_bqkv);

    int sms = 148;
    cudaDeviceGetAttribute(&sms, cudaDevAttrMultiProcessorCount, 0);

    cudaFuncSetAttribute(gemm_h<0>, cudaFuncAttributeMaxDynamicSharedMemorySize, GEMM_SMEM);
    cudaFuncSetAttribute(gemm_h<3>, cudaFuncAttributeMaxDynamicSharedMemorySize, GEMM_SMEM);
    cudaFuncSetAttribute(attn_mma, cudaFuncAttributeMaxDynamicSharedMemorySize, ATT_SMEM_BYTES);

    conv_h<<<(MROWS * HID / 4) / 256, 256>>>((const float4*)hs, (__half2*)hp);
    conv_w4<<<(4 * HID * HID / 4) / 256, 256>>>(
        (const float4*)wq, (const float4*)wk, (const float4*)wv, (const float4*)wo,
        (__half2*)wqkvp, (__half2*)wop);
    conv_b<<<12, 256>>>(bq, bk, bv, bqkvp);

    // QKV: 768 tiles, persistent on 2*sms CTAs
    const int qkv_tiles = (3 * HID / TBN) * (MROWS / TBM);   // 24 * 32 = 768
    int qkv_grid = 2 * sms; if (qkv_grid > qkv_tiles) qkv_grid = qkv_tiles;
    gemm_h<3><<<qkv_grid, 256, GEMM_SMEM>>>(hp, wqkvp, bqkvp, nullptr,
                                            qkv_tiles, 3 * HID / TBN);

    // attention: 1024 units, persistent on 3*sms CTAs
    int att_grid = 3 * sms; if (att_grid > NUNITS) att_grid = NUNITS;
    attn_mma<<<att_grid, ATHR, ATT_SMEM_BYTES>>>();

    // O-projection: 256 tiles, persistent on 2*sms CTAs
    const int o_tiles = (HID / TBN) * (MROWS / TBM);         // 8 * 32 = 256
    int o_grid = 2 * sms; if (o_grid > o_tiles) o_grid = o_tiles;
    gemm_h<0><<<o_grid, 256, GEMM_SMEM>>>(ap, wop, bo, out, o_tiles, HID / TBN);
}

// round 12
// speedup vs baseline: 1.0716x; 1.0716x over previous
#include <cuda_runtime.h>
#include <cuda_fp16.h>
#include <math.h>
#include <stdint.h>

// Problem constants
#define BATCH 2
#define SEQ   2048
#define HID   1024
#define NH    16
#define HD    64
#define MROWS (BATCH * SEQ)   // 4096

// Q pre-scale: HD^-0.5 * log2(e)  (softmax done in exp2 domain)
#define QSCALE (0.125f * 1.44269504088896f)

// ---------------- scratch (static device globals; no runtime alloc) ----------
__device__ __half g_q[MROWS * HID];      // pre-scaled by QSCALE
__device__ __half g_k[MROWS * HID];      // [seq][hid]
__device__ __half g_vt[MROWS * HID];     // [(b*NH+h)*HD+d][seq]
__device__ __half g_att[MROWS * HID];    // [seq][hid]
__device__ __half g_hs[MROWS * HID];
__device__ __half g_wqkv[3 * HID * HID]; // rows: [wq; wk; wv]
__device__ __half g_wo[HID * HID];
__device__ float  g_bqkv[3 * HID];

// ============================================================================
// helpers
// ============================================================================
__device__ __forceinline__ void cp16(uint32_t s, const void* g) {
    asm volatile("cp.async.cg.shared.global [%0], [%1], 16;" :: "r"(s), "l"(g));
}
#define CP_COMMIT() asm volatile("cp.async.commit_group;" ::: "memory")
template <int N>
__device__ __forceinline__ void cp_wait() {
    asm volatile("cp.async.wait_group %0;" :: "n"(N) : "memory");
}
__device__ __forceinline__ uint32_t smem_u32(const void* p) {
    uint32_t a;
    asm("{ .reg .u64 t; cvta.to.shared.u64 t, %1; cvt.u32.u64 %0, t; }"
        : "=r"(a) : "l"(p));
    return a;
}
__device__ __forceinline__ void mma_f16(
    float& c0, float& c1, float& c2, float& c3,
    uint32_t a0, uint32_t a1, uint32_t a2, uint32_t a3,
    uint32_t b0, uint32_t b1)
{
    asm volatile(
        "mma.sync.aligned.m16n8k16.row.col.f32.f16.f16.f32 "
        "{%0,%1,%2,%3}, {%4,%5,%6,%7}, {%8,%9}, {%0,%1,%2,%3};"
        : "+f"(c0), "+f"(c1), "+f"(c2), "+f"(c3)
        : "r"(a0), "r"(a1), "r"(a2), "r"(a3), "r"(b0), "r"(b1));
}
__device__ __forceinline__ void ldsm4(
    uint32_t& r0, uint32_t& r1, uint32_t& r2, uint32_t& r3, uint32_t a)
{
    asm volatile("ldmatrix.sync.aligned.m8n8.x4.shared.b16 {%0,%1,%2,%3}, [%4];"
                 : "=r"(r0), "=r"(r1), "=r"(r2), "=r"(r3) : "r"(a));
}
__device__ __forceinline__ uint32_t pack_h2(float a, float b) {
    __half2 h = __floats2half2_rn(a, b);
    return *(uint32_t*)&h;
}
__device__ __forceinline__ float ex2(float x) {
    float y;
    asm("ex2.approx.f32 %0, %1;" : "=f"(y) : "f"(x));
    return y;
}

// ============================================================================
// fused conversion kernel: hs + wq/wk/wv + wo + biases in ONE launch.
// Work layout (float4 granularity):
//   [0, 1M)            hs      -> g_hs (half)
//   [1M, 1M+768K)      w{q,k,v}-> g_wqkv (half)
//   [.., +256K)        wo      -> g_wo (half)
//   [.., +768)         b{q,k,v}-> g_bqkv (float, raw copy)
// ============================================================================
#define CV_HS   (MROWS * HID / 4)            // 1048576
#define CV_W    (HID * HID / 4)              // 262144
#define CV_TOT  (CV_HS + 4 * CV_W + 768)     // 2097920 + 768... computed below

__global__ void conv_all(
    const float4* __restrict__ hs,
    const float4* __restrict__ wq, const float4* __restrict__ wk,
    const float4* __restrict__ wv, const float4* __restrict__ wo,
    const float4* __restrict__ bq, const float4* __restrict__ bk,
    const float4* __restrict__ bv,
    __half2* __restrict__ hsh, __half2* __restrict__ wqkvh,
    __half2* __restrict__ woh, float4* __restrict__ bqkvf)
{
    int i = blockIdx.x * blockDim.x + threadIdx.x;
    if (i < CV_HS) {
        float4 v = hs[i];
        hsh[2 * i]     = __floats2half2_rn(v.x, v.y);
        hsh[2 * i + 1] = __floats2half2_rn(v.z, v.w);
        return;
    }
    i -= CV_HS;
    if (i < 3 * CV_W) {
        int seg = i / CV_W;
        int off = i - seg * CV_W;
        const float4* src = seg == 0 ? wq : seg == 1 ? wk : wv;
        float4 v = src[off];
        wqkvh[2 * i]     = __floats2half2_rn(v.x, v.y);
        wqkvh[2 * i + 1] = __floats2half2_rn(v.z, v.w);
        return;
    }
    i -= 3 * CV_W;
    if (i < CV_W) {
        float4 v = wo[i];
        woh[2 * i]     = __floats2half2_rn(v.x, v.y);
        woh[2 * i + 1] = __floats2half2_rn(v.z, v.w);
        return;
    }
    i -= CV_W;
    if (i < 768) {
        int seg = i >> 8;            // 0..2
        int off = i & 255;
        const float4* src = seg == 0 ? bq : seg == 1 ? bk : bv;
        bqkvf[i] = src[off];
    }
}

// ============================================================================
// fp16 GEMM: BK=64, 3-stage cp.async ring, ONE barrier per stage.  (R9 form)
// MODE 0: out f32 = acc + bias (O-projection)
// MODE 3: fused QKV epilogue, segment by global column
// ============================================================================
#define TBM 128
#define TBN 128
#define TBK 64
#define KSTAGES (HID / TBK)     // 16
#define ASTR 72                 // halfs per smem row (144B)
#define MATH2 (128 * ASTR)      // 9216 halfs per matrix per stage
#define MATB2 (MATH2 * 2)       // 18432 bytes
#define GSTAGES 3
#define GEMM_SMEM (GSTAGES * 2 * MATB2)   // 110592

__device__ __forceinline__ void g_load_stage(
    uint32_t sbase, int slot,
    const __half* __restrict__ X, const __half* __restrict__ W,
    int m0, int n0, int k0, int t)
{
    uint32_t aB = sbase + (uint32_t)(slot * 2) * MATB2;
    uint32_t bB = aB + MATB2;
    #pragma unroll
    for (int i = 0; i < 4; ++i) {
        int cid = t + (i << 8);          // 0..1023
        int r = cid >> 3;                // row 0..127
        int c = cid & 7;                 // 16B chunk 0..7
        uint32_t off = (uint32_t)r * (ASTR * 2) + (uint32_t)c * 16;
        cp16(aB + off, X + (size_t)(m0 + r) * HID + k0 + (c << 3));
        cp16(bB + off, W + (size_t)(n0 + r) * HID + k0 + (c << 3));
    }
}

template <int MODE>
__global__ __launch_bounds__(256, 2) void gemm_h(
    const __half* __restrict__ X, const __half* __restrict__ W,
    const float* __restrict__ bias, void* __restrict__ outv)
{
    extern __shared__ __align__(16) __half hsm[];
    const uint32_t sbase = smem_u32(hsm);

    const int t    = threadIdx.x;
    const int wid  = t >> 5;
    const int lane = t & 31;
    const int wr   = (wid >> 2) << 6;
    const int wc   = (wid & 3) << 5;
    const int m0   = blockIdx.y * TBM;
    const int n0   = blockIdx.x * TBN;
    const int lr   = lane >> 2;
    const int lc   = lane & 3;

    const int i8 = lane & 7, j4 = lane >> 3;
    const uint32_t aRow = (uint32_t)(((j4 & 1) << 3) + i8);
    const uint32_t aKo  = (uint32_t)((j4 >> 1) << 3);
    const uint32_t bRow = (uint32_t)(((j4 >> 1) << 3) + i8);
    const uint32_t bKo  = (uint32_t)((j4 & 1) << 3);

    float acc[4][4][4] = {};

    g_load_stage(sbase, 0, X, W, m0, n0, 0, t);
    CP_COMMIT();
    g_load_stage(sbase, 1, X, W, m0, n0, TBK, t);
    CP_COMMIT();

    int slot = 0;
    for (int s = 0; s < KSTAGES; ++s) {
        if (s + 1 < KSTAGES) cp_wait<1>(); else cp_wait<0>();
        __syncthreads();

        if (s + 2 < KSTAGES) {
            int nslot = slot + 2; if (nslot >= GSTAGES) nslot -= GSTAGES;
            g_load_stage(sbase, nslot, X, W, m0, n0, (s + 2) * TBK, t);
            CP_COMMIT();
        }

        const uint32_t aB = sbase + (uint32_t)(slot * 2) * MATB2;
        const uint32_t bB = aB + MATB2;

        #pragma unroll
        for (int kk = 0; kk < 4; ++kk) {
            const uint32_t ko = (uint32_t)(kk << 4);
            uint32_t af[4][4];
            #pragma unroll
            for (int mi = 0; mi < 4; ++mi)
                ldsm4(af[mi][0], af[mi][1], af[mi][2], af[mi][3],
                      aB + (((uint32_t)(wr + (mi << 4)) + aRow) * ASTR + ko + aKo) * 2);
            uint32_t bf[4][2];
            #pragma unroll
            for (int p = 0; p < 2; ++p)
                ldsm4(bf[2 * p][0], bf[2 * p][1], bf[2 * p + 1][0], bf[2 * p + 1][1],
                      bB + (((uint32_t)(wc + (p << 4)) + bRow) * ASTR + ko + bKo) * 2);
            #pragma unroll
            for (int mi = 0; mi < 4; ++mi)
                #pragma unroll
                for (int ni = 0; ni < 4; ++ni)
                    mma_f16(acc[mi][ni][0], acc[mi][ni][1],
                            acc[mi][ni][2], acc[mi][ni][3],
                            af[mi][0], af[mi][1], af[mi][2], af[mi][3],
                            bf[ni][0], bf[ni][1]);
        }

        if (++slot >= GSTAGES) slot = 0;
    }

    const int seg = n0 >> 10;

    #pragma unroll
    for (int mi = 0; mi < 4; ++mi) {
        #pragma unroll
        for (int ni = 0; ni < 4; ++ni) {
            const int row = m0 + wr + (mi << 4) + lr;
            const int col = n0 + wc + (ni << 3) + (lc << 1);
            float2 b01 = *(const float2*)&bias[col];
            float v00 = acc[mi][ni][0] + b01.x;
            float v01 = acc[mi][ni][1] + b01.y;
            float v10 = acc[mi][ni][2] + b01.x;
            float v11 = acc[mi][ni][3] + b01.y;
            if (MODE == 0) {
                float* out = (float*)outv;
                *(float2*)&out[(size_t)row * HID + col] = make_float2(v00, v01);
                *(float2*)&out[(size_t)(row + 8) * HID + col] = make_float2(v10, v11);
            } else {
                const int c = col & 1023;
                if (seg == 0) {
                    *(uint32_t*)&g_q[(size_t)row * HID + c] =
                        pack_h2(QSCALE * v00, QSCALE * v01);
                    *(uint32_t*)&g_q[(size_t)(row + 8) * HID + c] =
                        pack_h2(QSCALE * v10, QSCALE * v11);
                } else if (seg == 1) {
                    *(uint32_t*)&g_k[(size_t)row * HID + c] = pack_h2(v00, v01);
                    *(uint32_t*)&g_k[(size_t)(row + 8) * HID + c] = pack_h2(v10, v11);
                } else {
                    const int b0i = row >> 11, s0 = row & 2047;
                    const int b1i = (row + 8) >> 11, s1 = (row + 8) & 2047;
                    const int h0 = c >> 6, d0 = c & 63;
                    const int h1 = (c + 1) >> 6, d1 = (c + 1) & 63;
                    g_vt[((size_t)(b0i * NH + h0) * HD + d0) * SEQ + s0] = __float2half(v00);
                    g_vt[((size_t)(b0i * NH + h1) * HD + d1) * SEQ + s0] = __float2half(v01);
                    g_vt[((size_t)(b1i * NH + h0) * HD + d0) * SEQ + s1] = __float2half(v10);
                    g_vt[((size_t)(b1i * NH + h1) * HD + d1) * SEQ + s1] = __float2half(v11);
                }
            }
        }
    }
}

// ============================================================================
// Flash attention (R9 form): QT=64, 4 warps, 3 CTAs/SM, 3-stage KV ring,
// one barrier per tile, pipelined fragment loads.
// ============================================================================
#define QT    64
#define ATHR  128
#define KT    64
#define NKT   (SEQ / KT)            // 32
#define HSTR  72                    // halfs per smem row (144B)
#define KSTG2 (KT * HSTR)           // 4608 halfs per stage
#define ASTAGES 3
#define VBASE2 (ASTAGES * KSTG2)    // 13824
#define PBASE2 (VBASE2 + ASTAGES * KSTG2)  // 27648
#define PWARP2 (16 * HSTR)          // 1152
#define ATT_SMEM_BYTES ((PBASE2 + 4 * PWARP2) * 2)  // 64512

__device__ __forceinline__ void a_load_kv(
    uint32_t sbase, int slot, int b, int h, int k0, int t)
{
    const uint32_t kB = sbase + (uint32_t)slot * (KSTG2 * 2);
    const uint32_t vB = sbase + (uint32_t)(VBASE2 + slot * KSTG2) * 2;
    #pragma unroll
    for (int i = 0; i < 4; ++i) {
        int cid = t + (i << 7);
        int r = cid >> 3;
        int c = cid & 7;
        cp16(kB + (uint32_t)r * (HSTR * 2) + (uint32_t)c * 16,
             g_k + (size_t)(b * SEQ + k0 + r) * HID + h * HD + (c << 3));
        cp16(vB + (uint32_t)r * (HSTR * 2) + (uint32_t)c * 16,
             g_vt + ((size_t)(b * NH + h) * HD + r) * SEQ + k0 + (c << 3));
    }
}

__global__ __launch_bounds__(ATHR, 3) void attn_mma()
{
    extern __shared__ __align__(16) __half hsm[];
    const uint32_t sbase = smem_u32(hsm);

    const int t    = threadIdx.x;
    const int wid  = t >> 5;
    const int lane = t & 31;
    const int lr   = lane >> 2;
    const int lc   = lane & 3;

    const int i8 = lane & 7, j4 = lane >> 3;
    const uint32_t aRow = (uint32_t)(((j4 & 1) << 3) + i8);
    const uint32_t aKo  = (uint32_t)((j4 >> 1) << 3);
    const uint32_t bRow = (uint32_t)(((j4 >> 1) << 3) + i8);
    const uint32_t bKo  = (uint32_t)((j4 & 1) << 3);

    const int b  = blockIdx.z;
    const int h  = blockIdx.y;
    const int q0 = blockIdx.x * QT;
    const int wq = wid << 4;

    uint32_t qf[4][4];
    {
        const __half* Qg = g_q + (size_t)(b * SEQ + q0 + wq) * HID + h * HD;
        #pragma unroll
        for (int ks = 0; ks < 4; ++ks) {
            const int ko = (ks << 4) + (lc << 1);
            qf[ks][0] = *(const uint32_t*)&Qg[(size_t)lr * HID + ko];
            qf[ks][1] = *(const uint32_t*)&Qg[(size_t)(lr + 8) * HID + ko];
            qf[ks][2] = *(const uint32_t*)&Qg[(size_t)lr * HID + ko + 8];
            qf[ks][3] = *(const uint32_t*)&Qg[(size_t)(lr + 8) * HID + ko + 8];
        }
    }

    float O[8][4] = {};
    float mrow[2] = {-1e30f, -1e30f};
    float lrow[2] = {0.f, 0.f};

    a_load_kv(sbase, 0, b, h, 0, t);
    CP_COMMIT();
    a_load_kv(sbase, 1, b, h, KT, t);
    CP_COMMIT();

    const uint32_t pB = sbase + (uint32_t)(PBASE2 + wid * PWARP2) * 2;
    __half* sPw = hsm + PBASE2 + wid * PWARP2;

    int slot = 0;
    for (int kt = 0; kt < NKT; ++kt) {
        if (kt + 1 < NKT) cp_wait<1>(); else cp_wait<0>();
        __syncthreads();

        if (kt + 2 < NKT) {
            int nslot = slot + 2; if (nslot >= ASTAGES) nslot -= ASTAGES;
            a_load_kv(sbase, nslot, b, h, (kt + 2) * KT, t);
            CP_COMMIT();
        }

        const uint32_t kB = sbase + (uint32_t)slot * (KSTG2 * 2);
        const uint32_t vB = sbase + (uint32_t)(VBASE2 + slot * KSTG2) * 2;

        // ---- S = Qs @ K^T, pipelined K-fragment loads ----
        float S[8][4] = {};
        {
            uint32_t kf0[4], kf1[4];
            ldsm4(kf0[0], kf0[1], kf0[2], kf0[3], kB + (bRow * HSTR + bKo) * 2);
            #pragma unroll
            for (int idx = 0; idx < 16; ++idx) {
                const int ks = idx >> 2, p = idx & 3;
                uint32_t* cur = (idx & 1) ? kf1 : kf0;
                uint32_t* nxt = (idx & 1) ? kf0 : kf1;
                if (idx < 15) {
                    const int nks = (idx + 1) >> 2, np = (idx + 1) & 3;
                    ldsm4(nxt[0], nxt[1], nxt[2], nxt[3],
                          kB + (((uint32_t)(np << 4) + bRow) * HSTR
                                + (uint32_t)(nks << 4) + bKo) * 2);
                }
                mma_f16(S[2*p][0], S[2*p][1], S[2*p][2], S[2*p][3],
                        qf[ks][0], qf[ks][1], qf[ks][2], qf[ks][3],
                        cur[0], cur[1]);
                mma_f16(S[2*p+1][0], S[2*p+1][1], S[2*p+1][2], S[2*p+1][3],
                        qf[ks][0], qf[ks][1], qf[ks][2], qf[ks][3],
                        cur[2], cur[3]);
            }
        }

        // ---- online softmax (exp2 domain) ----
        #pragma unroll
        for (int r = 0; r < 2; ++r) {
            const int e0 = r << 1, e1 = e0 + 1;
            float mt = -1e30f;
            #pragma unroll
            for (int nt = 0; nt < 8; ++nt)
                mt = fmaxf(mt, fmaxf(S[nt][e0], S[nt][e1]));
            mt = fmaxf(mt, __shfl_xor_sync(0xffffffffu, mt, 1));
            mt = fmaxf(mt, __shfl_xor_sync(0xffffffffu, mt, 2));
            float mnew = fmaxf(mrow[r], mt);
            float corr = ex2(mrow[r] - mnew);
            float rs = 0.f;
            #pragma unroll
            for (int nt = 0; nt < 8; ++nt) {
                float p0 = ex2(S[nt][e0] - mnew);
                float p1 = ex2(S[nt][e1] - mnew);
                S[nt][e0] = p0; S[nt][e1] = p1;
                rs += p0 + p1;
            }
            rs += __shfl_xor_sync(0xffffffffu, rs, 1);
            rs += __shfl_xor_sync(0xffffffffu, rs, 2);
            lrow[r] = lrow[r] * corr + rs;
            mrow[r] = mnew;
            #pragma unroll
            for (int nt = 0; nt < 8; ++nt) {
                O[nt][e0] *= corr;
                O[nt][e1] *= corr;
            }
        }

        // ---- P -> per-warp smem ----
        #pragma unroll
        for (int nt = 0; nt < 8; ++nt) {
            const int col = (nt << 3) + (lc << 1);
            *(uint32_t*)&sPw[lr * HSTR + col]       = pack_h2(S[nt][0], S[nt][1]);
            *(uint32_t*)&sPw[(lr + 8) * HSTR + col] = pack_h2(S[nt][2], S[nt][3]);
        }
        __syncwarp();

        // ---- O += P @ V, pipelined P/V fragment loads ----
        {
            uint32_t af0[4], af1[4], vf0[4], vf1[4];
            ldsm4(af0[0], af0[1], af0[2], af0[3], pB + (aRow * HSTR + aKo) * 2);
            ldsm4(vf0[0], vf0[1], vf0[2], vf0[3], vB + (bRow * HSTR + bKo) * 2);
            #pragma unroll
            for (int idx = 0; idx < 16; ++idx) {
                const int ks = idx >> 2, p = idx & 3;
                uint32_t* cura = (ks & 1) ? af1 : af0;
                uint32_t* nxta = (ks & 1) ? af0 : af1;
                uint32_t* curv = (idx & 1) ? vf1 : vf0;
                uint32_t* nxtv = (idx & 1) ? vf0 : vf1;
                if (p == 0 && ks < 3)
                    ldsm4(nxta[0], nxta[1], nxta[2], nxta[3],
                          pB + (aRow * HSTR + (uint32_t)((ks + 1) << 4) + aKo) * 2);
                if (idx < 15) {
                    const int nks = (idx + 1) >> 2, np = (idx + 1) & 3;
                    ldsm4(nxtv[0], nxtv[1], nxtv[2], nxtv[3],
                          vB + (((uint32_t)(np << 4) + bRow) * HSTR
                                + (uint32_t)(nks << 4) + bKo) * 2);
                }
                mma_f16(O[2*p][0], O[2*p][1], O[2*p][2], O[2*p][3],
                        cura[0], cura[1], cura[2], cura[3], curv[0], curv[1]);
                mma_f16(O[2*p+1][0], O[2*p+1][1], O[2*p+1][2], O[2*p+1][3],
                        cura[0], cura[1], cura[2], cura[3], curv[2], curv[3]);
            }
        }

        if (++slot >= ASTAGES) slot = 0;
    }

    // ---- normalize + store half ----
    const float inv0 = 1.f / lrow[0];
    const float inv1 = 1.f / lrow[1];
    __half* Og = g_att + (size_t)(b * SEQ + q0 + wq) * HID + h * HD;
    #pragma unroll
    for (int nt = 0; nt < 8; ++nt) {
        const int col = (nt << 3) + (lc << 1);
        *(uint32_t*)&Og[(size_t)lr * HID + col] =
            pack_h2(O[nt][0] * inv0, O[nt][1] * inv0);
        *(uint32_t*)&Og[(size_t)(lr + 8) * HID + col] =
            pack_h2(O[nt][2] * inv1, O[nt][3] * inv1);
    }
}

// ---------------- launch ----------------------------------------------------
extern "C" void kernel_launch(void* const* d_in, const int* in_sizes, int n_in,
                              void* d_out, int out_size)
{
    const float* hs = (const float*)d_in[0];
    const float* wq = (const float*)d_in[1];
    const float* bq = (const float*)d_in[2];
    const float* wk = (const float*)d_in[3];
    const float* bk = (const float*)d_in[4];
    const float* wv = (const float*)d_in[5];
    const float* bv = (const float*)d_in[6];
    const float* wo = (const float*)d_in[7];
    const float* bo = (const float*)d_in[8];
    float* out = (float*)d_out;

    __half *hp, *wqkvp, *wop, *ap;
    float *bqkvp;
    cudaGetSymbolAddress((void**)&hp, g_hs);
    cudaGetSymbolAddress((void**)&wqkvp, g_wqkv);
    cudaGetSymbolAddress((void**)&wop, g_wo);
    cudaGetSymbolAddress((void**)&ap, g_att);
    cudaGetSymbolAddress((void**)&bqkvp, g_bqkv);

    cudaFuncSetAttribute(gemm_h<0>, cudaFuncAttributeMaxDynamicSharedMemorySize, GEMM_SMEM);
    cudaFuncSetAttribute(gemm_h<3>, cudaFuncAttributeMaxDynamicSharedMemorySize, GEMM_SMEM);
    cudaFuncSetAttribute(attn_mma, cudaFuncAttributeMaxDynamicSharedMemorySize, ATT_SMEM_BYTES);

    // fused conversion (1 launch): hs + 4 weights + biases
    const int cv_total = CV_HS + 4 * CV_W + 768;
    conv_all<<<(cv_total + 255) / 256, 256>>>(
        (const float4*)hs,
        (const float4*)wq, (const float4*)wk, (const float4*)wv, (const float4*)wo,
        (const float4*)bq, (const float4*)bk, (const float4*)bv,
        (__half2*)hp, (__half2*)wqkvp, (__half2*)wop, (float4*)bqkvp);

    dim3 qkvgrid(3 * HID / TBN, MROWS / TBM);  // (24, 32)
    gemm_h<3><<<qkvgrid, 256, GEMM_SMEM>>>(hp, wqkvp, bqkvp, nullptr);

    dim3 agrid(SEQ / QT, NH, BATCH);           // (32, 16, 2)
    attn_mma<<<agrid, ATHR, ATT_SMEM_BYTES>>>();

    dim3 ogrid(HID / TBN, MROWS / TBM);        // (8, 32)
    gemm_h<0><<<ogrid, 256, GEMM_SMEM>>>(ap, wop, bo, out);
}

// round 13
// speedup vs baseline: 1.1477x; 1.0711x over previous
#include <cuda_runtime.h>
#include <cuda_fp16.h>
#include <math.h>
#include <stdint.h>

// Problem constants
#define BATCH 2
#define SEQ   2048
#define HID   1024
#define NH    16
#define HD    64
#define MROWS (BATCH * SEQ)   // 4096

// Q pre-scale: HD^-0.5 * log2(e)  (softmax done in exp2 domain)
#define QSCALE (0.125f * 1.44269504088896f)

// ---------------- scratch (static device globals; no runtime alloc) ----------
__device__ __half g_q[MROWS * HID];      // pre-scaled by QSCALE
__device__ __half g_k[MROWS * HID];      // [seq][hid]
__device__ __half g_vt[MROWS * HID];     // [(b*NH+h)*HD+d][seq]
__device__ __half g_att[MROWS * HID];    // [seq][hid]
__device__ __half g_hs[MROWS * HID];
__device__ __half g_wqkv[3 * HID * HID]; // rows: [wq; wk; wv]
__device__ __half g_wo[HID * HID];
__device__ float  g_bqkv[3 * HID];

// ============================================================================
// helpers
// ============================================================================
__device__ __forceinline__ void cp16(uint32_t s, const void* g) {
    asm volatile("cp.async.cg.shared.global [%0], [%1], 16;" :: "r"(s), "l"(g));
}
#define CP_COMMIT() asm volatile("cp.async.commit_group;" ::: "memory")
template <int N>
__device__ __forceinline__ void cp_wait() {
    asm volatile("cp.async.wait_group %0;" :: "n"(N) : "memory");
}
__device__ __forceinline__ uint32_t smem_u32(const void* p) {
    uint32_t a;
    asm("{ .reg .u64 t; cvta.to.shared.u64 t, %1; cvt.u32.u64 %0, t; }"
        : "=r"(a) : "l"(p));
    return a;
}
__device__ __forceinline__ void mma_f16(
    float& c0, float& c1, float& c2, float& c3,
    uint32_t a0, uint32_t a1, uint32_t a2, uint32_t a3,
    uint32_t b0, uint32_t b1)
{
    asm volatile(
        "mma.sync.aligned.m16n8k16.row.col.f32.f16.f16.f32 "
        "{%0,%1,%2,%3}, {%4,%5,%6,%7}, {%8,%9}, {%0,%1,%2,%3};"
        : "+f"(c0), "+f"(c1), "+f"(c2), "+f"(c3)
        : "r"(a0), "r"(a1), "r"(a2), "r"(a3), "r"(b0), "r"(b1));
}
__device__ __forceinline__ void ldsm4(
    uint32_t& r0, uint32_t& r1, uint32_t& r2, uint32_t& r3, uint32_t a)
{
    asm volatile("ldmatrix.sync.aligned.m8n8.x4.shared.b16 {%0,%1,%2,%3}, [%4];"
                 : "=r"(r0), "=r"(r1), "=r"(r2), "=r"(r3) : "r"(a));
}
__device__ __forceinline__ uint32_t pack_h2(float a, float b) {
    __half2 h = __floats2half2_rn(a, b);
    return *(uint32_t*)&h;
}
__device__ __forceinline__ float ex2(float x) {
    float y;
    asm("ex2.approx.f32 %0, %1;" : "=f"(y) : "f"(x));
    return y;
}

// ============================================================================
// fused conversion kernel: hs + wq/wk/wv + wo + biases in ONE launch.
// ============================================================================
#define CV_HS   (MROWS * HID / 4)            // 1048576
#define CV_W    (HID * HID / 4)              // 262144

__global__ void conv_all(
    const float4* __restrict__ hs,
    const float4* __restrict__ wq, const float4* __restrict__ wk,
    const float4* __restrict__ wv, const float4* __restrict__ wo,
    const float4* __restrict__ bq, const float4* __restrict__ bk,
    const float4* __restrict__ bv,
    __half2* __restrict__ hsh, __half2* __restrict__ wqkvh,
    __half2* __restrict__ woh, float4* __restrict__ bqkvf)
{
    int i = blockIdx.x * blockDim.x + threadIdx.x;
    if (i < CV_HS) {
        float4 v = hs[i];
        hsh[2 * i]     = __floats2half2_rn(v.x, v.y);
        hsh[2 * i + 1] = __floats2half2_rn(v.z, v.w);
        return;
    }
    i -= CV_HS;
    if (i < 3 * CV_W) {
        int seg = i / CV_W;
        int off = i - seg * CV_W;
        const float4* src = seg == 0 ? wq : seg == 1 ? wk : wv;
        float4 v = src[off];
        wqkvh[2 * i]     = __floats2half2_rn(v.x, v.y);
        wqkvh[2 * i + 1] = __floats2half2_rn(v.z, v.w);
        return;
    }
    i -= 3 * CV_W;
    if (i < CV_W) {
        float4 v = wo[i];
        woh[2 * i]     = __floats2half2_rn(v.x, v.y);
        woh[2 * i + 1] = __floats2half2_rn(v.z, v.w);
        return;
    }
    i -= CV_W;
    if (i < 768) {
        int seg = i >> 8;
        int off = i & 255;
        const float4* src = seg == 0 ? bq : seg == 1 ? bk : bv;
        bqkvf[i] = src[off];
    }
}

// ============================================================================
// fp16 GEMM: BK=64, 3-stage cp.async ring, ONE barrier per stage.  (R9 form)
// MODE 0: out f32 = acc + bias (O-projection)
// MODE 3: fused QKV epilogue, segment by global column
// ============================================================================
#define TBM 128
#define TBN 128
#define TBK 64
#define KSTAGES (HID / TBK)     // 16
#define ASTR 72                 // halfs per smem row (144B)
#define MATH2 (128 * ASTR)      // 9216 halfs per matrix per stage
#define MATB2 (MATH2 * 2)       // 18432 bytes
#define GSTAGES 3
#define GEMM_SMEM (GSTAGES * 2 * MATB2)   // 110592

__device__ __forceinline__ void g_load_stage(
    uint32_t sbase, int slot,
    const __half* __restrict__ X, const __half* __restrict__ W,
    int m0, int n0, int k0, int t)
{
    uint32_t aB = sbase + (uint32_t)(slot * 2) * MATB2;
    uint32_t bB = aB + MATB2;
    #pragma unroll
    for (int i = 0; i < 4; ++i) {
        int cid = t + (i << 8);          // 0..1023
        int r = cid >> 3;                // row 0..127
        int c = cid & 7;                 // 16B chunk 0..7
        uint32_t off = (uint32_t)r * (ASTR * 2) + (uint32_t)c * 16;
        cp16(aB + off, X + (size_t)(m0 + r) * HID + k0 + (c << 3));
        cp16(bB + off, W + (size_t)(n0 + r) * HID + k0 + (c << 3));
    }
}

template <int MODE>
__global__ __launch_bounds__(256, 2) void gemm_h(
    const __half* __restrict__ X, const __half* __restrict__ W,
    const float* __restrict__ bias, void* __restrict__ outv)
{
    extern __shared__ __align__(16) __half hsm[];
    const uint32_t sbase = smem_u32(hsm);

    const int t    = threadIdx.x;
    const int wid  = t >> 5;
    const int lane = t & 31;
    const int wr   = (wid >> 2) << 6;
    const int wc   = (wid & 3) << 5;
    const int m0   = blockIdx.y * TBM;
    const int n0   = blockIdx.x * TBN;
    const int lr   = lane >> 2;
    const int lc   = lane & 3;

    const int i8 = lane & 7, j4 = lane >> 3;
    const uint32_t aRow = (uint32_t)(((j4 & 1) << 3) + i8);
    const uint32_t aKo  = (uint32_t)((j4 >> 1) << 3);
    const uint32_t bRow = (uint32_t)(((j4 >> 1) << 3) + i8);
    const uint32_t bKo  = (uint32_t)((j4 & 1) << 3);

    float acc[4][4][4] = {};

    g_load_stage(sbase, 0, X, W, m0, n0, 0, t);
    CP_COMMIT();
    g_load_stage(sbase, 1, X, W, m0, n0, TBK, t);
    CP_COMMIT();

    int slot = 0;
    for (int s = 0; s < KSTAGES; ++s) {
        if (s + 1 < KSTAGES) cp_wait<1>(); else cp_wait<0>();
        __syncthreads();

        if (s + 2 < KSTAGES) {
            int nslot = slot + 2; if (nslot >= GSTAGES) nslot -= GSTAGES;
            g_load_stage(sbase, nslot, X, W, m0, n0, (s + 2) * TBK, t);
            CP_COMMIT();
        }

        const uint32_t aB = sbase + (uint32_t)(slot * 2) * MATB2;
        const uint32_t bB = aB + MATB2;

        #pragma unroll
        for (int kk = 0; kk < 4; ++kk) {
            const uint32_t ko = (uint32_t)(kk << 4);
            uint32_t af[4][4];
            #pragma unroll
            for (int mi = 0; mi < 4; ++mi)
                ldsm4(af[mi][0], af[mi][1], af[mi][2], af[mi][3],
                      aB + (((uint32_t)(wr + (mi << 4)) + aRow) * ASTR + ko + aKo) * 2);
            uint32_t bf[4][2];
            #pragma unroll
            for (int p = 0; p < 2; ++p)
                ldsm4(bf[2 * p][0], bf[2 * p][1], bf[2 * p + 1][0], bf[2 * p + 1][1],
                      bB + (((uint32_t)(wc + (p << 4)) + bRow) * ASTR + ko + bKo) * 2);
            #pragma unroll
            for (int mi = 0; mi < 4; ++mi)
                #pragma unroll
                for (int ni = 0; ni < 4; ++ni)
                    mma_f16(acc[mi][ni][0], acc[mi][ni][1],
                            acc[mi][ni][2], acc[mi][ni][3],
                            af[mi][0], af[mi][1], af[mi][2], af[mi][3],
                            bf[ni][0], bf[ni][1]);
        }

        if (++slot >= GSTAGES) slot = 0;
    }

    const int seg = n0 >> 10;

    #pragma unroll
    for (int mi = 0; mi < 4; ++mi) {
        #pragma unroll
        for (int ni = 0; ni < 4; ++ni) {
            const int row = m0 + wr + (mi << 4) + lr;
            const int col = n0 + wc + (ni << 3) + (lc << 1);
            float2 b01 = *(const float2*)&bias[col];
            float v00 = acc[mi][ni][0] + b01.x;
            float v01 = acc[mi][ni][1] + b01.y;
            float v10 = acc[mi][ni][2] + b01.x;
            float v11 = acc[mi][ni][3] + b01.y;
            if (MODE == 0) {
                float* out = (float*)outv;
                *(float2*)&out[(size_t)row * HID + col] = make_float2(v00, v01);
                *(float2*)&out[(size_t)(row + 8) * HID + col] = make_float2(v10, v11);
            } else {
                const int c = col & 1023;
                if (seg == 0) {
                    *(uint32_t*)&g_q[(size_t)row * HID + c] =
                        pack_h2(QSCALE * v00, QSCALE * v01);
                    *(uint32_t*)&g_q[(size_t)(row + 8) * HID + c] =
                        pack_h2(QSCALE * v10, QSCALE * v11);
                } else if (seg == 1) {
                    *(uint32_t*)&g_k[(size_t)row * HID + c] = pack_h2(v00, v01);
                    *(uint32_t*)&g_k[(size_t)(row + 8) * HID + c] = pack_h2(v10, v11);
                } else {
                    const int b0i = row >> 11, s0 = row & 2047;
                    const int b1i = (row + 8) >> 11, s1 = (row + 8) & 2047;
                    const int h0 = c >> 6, d0 = c & 63;
                    const int h1 = (c + 1) >> 6, d1 = (c + 1) & 63;
                    g_vt[((size_t)(b0i * NH + h0) * HD + d0) * SEQ + s0] = __float2half(v00);
                    g_vt[((size_t)(b0i * NH + h1) * HD + d1) * SEQ + s0] = __float2half(v01);
                    g_vt[((size_t)(b1i * NH + h0) * HD + d0) * SEQ + s1] = __float2half(v10);
                    g_vt[((size_t)(b1i * NH + h1) * HD + d1) * SEQ + s1] = __float2half(v11);
                }
            }
        }
    }
}

// ============================================================================
// Flash attention: QT=64, 4 warps, 4 CTAs/SM, 3-stage KV ring,
// register-direct PV (no P smem round-trip).
// ============================================================================
#define QT    64
#define ATHR  128
#define KT    64
#define NKT   (SEQ / KT)            // 32
#define HSTR  72                    // halfs per smem row (144B)
#define KSTG2 (KT * HSTR)           // 4608 halfs per stage
#define ASTAGES 3
#define VBASE2 (ASTAGES * KSTG2)    // 13824
#define ATT_SMEM_BYTES (2 * ASTAGES * KSTG2 * 2)  // 55296

__device__ __forceinline__ void a_load_kv(
    uint32_t sbase, int slot, int b, int h, int k0, int t)
{
    const uint32_t kB = sbase + (uint32_t)slot * (KSTG2 * 2);
    const uint32_t vB = sbase + (uint32_t)(VBASE2 + slot * KSTG2) * 2;
    #pragma unroll
    for (int i = 0; i < 4; ++i) {
        int cid = t + (i << 7);
        int r = cid >> 3;
        int c = cid & 7;
        cp16(kB + (uint32_t)r * (HSTR * 2) + (uint32_t)c * 16,
             g_k + (size_t)(b * SEQ + k0 + r) * HID + h * HD + (c << 3));
        cp16(vB + (uint32_t)r * (HSTR * 2) + (uint32_t)c * 16,
             g_vt + ((size_t)(b * NH + h) * HD + r) * SEQ + k0 + (c << 3));
    }
}

__global__ __launch_bounds__(ATHR, 4) void attn_mma()
{
    extern __shared__ __align__(16) __half hsm[];
    const uint32_t sbase = smem_u32(hsm);

    const int t    = threadIdx.x;
    const int wid  = t >> 5;
    const int lane = t & 31;

    const int i8 = lane & 7, j4 = lane >> 3;
    const uint32_t bRow = (uint32_t)(((j4 >> 1) << 3) + i8);
    const uint32_t bKo  = (uint32_t)((j4 & 1) << 3);

    const int b  = blockIdx.z;
    const int h  = blockIdx.y;
    const int q0 = blockIdx.x * QT;
    const int wq = wid << 4;
    const int lr = lane >> 2;
    const int lc = lane & 3;

    uint32_t qf[4][4];
    {
        const __half* Qg = g_q + (size_t)(b * SEQ + q0 + wq) * HID + h * HD;
        #pragma unroll
        for (int ks = 0; ks < 4; ++ks) {
            const int ko = (ks << 4) + (lc << 1);
            qf[ks][0] = *(const uint32_t*)&Qg[(size_t)lr * HID + ko];
            qf[ks][1] = *(const uint32_t*)&Qg[(size_t)(lr + 8) * HID + ko];
            qf[ks][2] = *(const uint32_t*)&Qg[(size_t)lr * HID + ko + 8];
            qf[ks][3] = *(const uint32_t*)&Qg[(size_t)(lr + 8) * HID + ko + 8];
        }
    }

    float O[8][4] = {};
    float mrow[2] = {-1e30f, -1e30f};
    float lrow[2] = {0.f, 0.f};

    a_load_kv(sbase, 0, b, h, 0, t);
    CP_COMMIT();
    a_load_kv(sbase, 1, b, h, KT, t);
    CP_COMMIT();

    int slot = 0;
    for (int kt = 0; kt < NKT; ++kt) {
        if (kt + 1 < NKT) cp_wait<1>(); else cp_wait<0>();
        __syncthreads();

        if (kt + 2 < NKT) {
            int nslot = slot + 2; if (nslot >= ASTAGES) nslot -= ASTAGES;
            a_load_kv(sbase, nslot, b, h, (kt + 2) * KT, t);
            CP_COMMIT();
        }

        const uint32_t kB = sbase + (uint32_t)slot * (KSTG2 * 2);
        const uint32_t vB = sbase + (uint32_t)(VBASE2 + slot * KSTG2) * 2;

        // ---- S = Qs @ K^T, pipelined K-fragment loads ----
        float S[8][4] = {};
        {
            uint32_t kf0[4], kf1[4];
            ldsm4(kf0[0], kf0[1], kf0[2], kf0[3], kB + (bRow * HSTR + bKo) * 2);
            #pragma unroll
            for (int idx = 0; idx < 16; ++idx) {
                const int ks = idx >> 2, p = idx & 3;
                uint32_t* cur = (idx & 1) ? kf1 : kf0;
                uint32_t* nxt = (idx & 1) ? kf0 : kf1;
                if (idx < 15) {
                    const int nks = (idx + 1) >> 2, np = (idx + 1) & 3;
                    ldsm4(nxt[0], nxt[1], nxt[2], nxt[3],
                          kB + (((uint32_t)(np << 4) + bRow) * HSTR
                                + (uint32_t)(nks << 4) + bKo) * 2);
                }
                mma_f16(S[2*p][0], S[2*p][1], S[2*p][2], S[2*p][3],
                        qf[ks][0], qf[ks][1], qf[ks][2], qf[ks][3],
                        cur[0], cur[1]);
                mma_f16(S[2*p+1][0], S[2*p+1][1], S[2*p+1][2], S[2*p+1][3],
                        qf[ks][0], qf[ks][1], qf[ks][2], qf[ks][3],
                        cur[2], cur[3]);
            }
        }

        // ---- online softmax (exp2 domain) ----
        #pragma unroll
        for (int r = 0; r < 2; ++r) {
            const int e0 = r << 1, e1 = e0 + 1;
            float mt = -1e30f;
            #pragma unroll
            for (int nt = 0; nt < 8; ++nt)
                mt = fmaxf(mt, fmaxf(S[nt][e0], S[nt][e1]));
            mt = fmaxf(mt, __shfl_xor_sync(0xffffffffu, mt, 1));
            mt = fmaxf(mt, __shfl_xor_sync(0xffffffffu, mt, 2));
            float mnew = fmaxf(mrow[r], mt);
            float corr = ex2(mrow[r] - mnew);
            float rs = 0.f;
            #pragma unroll
            for (int nt = 0; nt < 8; ++nt) {
                float p0 = ex2(S[nt][e0] - mnew);
                float p1 = ex2(S[nt][e1] - mnew);
                S[nt][e0] = p0; S[nt][e1] = p1;
                rs += p0 + p1;
            }
            rs += __shfl_xor_sync(0xffffffffu, rs, 1);
            rs += __shfl_xor_sync(0xffffffffu, rs, 2);
            lrow[r] = lrow[r] * corr + rs;
            mrow[r] = mnew;
            #pragma unroll
            for (int nt = 0; nt < 8; ++nt) {
                O[nt][e0] *= corr;
                O[nt][e1] *= corr;
            }
        }

        // ---- O += P @ V : A fragments packed DIRECTLY from S registers ----
        #pragma unroll
        for (int ks = 0; ks < 4; ++ks) {
            const uint32_t a0 = pack_h2(S[2*ks][0],   S[2*ks][1]);
            const uint32_t a1 = pack_h2(S[2*ks][2],   S[2*ks][3]);
            const uint32_t a2 = pack_h2(S[2*ks+1][0], S[2*ks+1][1]);
            const uint32_t a3 = pack_h2(S[2*ks+1][2], S[2*ks+1][3]);
            const uint32_t ko = (uint32_t)(ks << 4);
            #pragma unroll
            for (int p = 0; p < 4; ++p) {
                uint32_t v0, v1, v2, v3;
                ldsm4(v0, v1, v2, v3,
                      vB + (((uint32_t)(p << 4) + bRow) * HSTR + ko + bKo) * 2);
                mma_f16(O[2*p][0], O[2*p][1], O[2*p][2], O[2*p][3],
                        a0, a1, a2, a3, v0, v1);
                mma_f16(O[2*p+1][0], O[2*p+1][1], O[2*p+1][2], O[2*p+1][3],
                        a0, a1, a2, a3, v2, v3);
            }
        }

        if (++slot >= ASTAGES) slot = 0;
    }

    // ---- normalize + store half ----
    const float inv0 = 1.f / lrow[0];
    const float inv1 = 1.f / lrow[1];
    __half* Og = g_att + (size_t)(b * SEQ + q0 + wq) * HID + h * HD;
    #pragma unroll
    for (int nt = 0; nt < 8; ++nt) {
        const int col = (nt << 3) + (lc << 1);
        *(uint32_t*)&Og[(size_t)lr * HID + col] =
            pack_h2(O[nt][0] * inv0, O[nt][1] * inv0);
        *(uint32_t*)&Og[(size_t)(lr + 8) * HID + col] =
            pack_h2(O[nt][2] * inv1, O[nt][3] * inv1);
    }
}

// ---------------- launch ----------------------------------------------------
extern "C" void kernel_launch(void* const* d_in, const int* in_sizes, int n_in,
                              void* d_out, int out_size)
{
    const float* hs = (const float*)d_in[0];
    const float* wq = (const float*)d_in[1];
    const float* bq = (const float*)d_in[2];
    const float* wk = (const float*)d_in[3];
    const float* bk = (const float*)d_in[4];
    const float* wv = (const float*)d_in[5];
    const float* bv = (const float*)d_in[6];
    const float* wo = (const float*)d_in[7];
    const float* bo = (const float*)d_in[8];
    float* out = (float*)d_out;

    __half *hp, *wqkvp, *wop, *ap;
    float *bqkvp;
    cudaGetSymbolAddress((void**)&hp, g_hs);
    cudaGetSymbolAddress((void**)&wqkvp, g_wqkv);
    cudaGetSymbolAddress((void**)&wop, g_wo);
    cudaGetSymbolAddress((void**)&ap, g_att);
    cudaGetSymbolAddress((void**)&bqkvp, g_bqkv);

    cudaFuncSetAttribute(gemm_h<0>, cudaFuncAttributeMaxDynamicSharedMemorySize, GEMM_SMEM);
    cudaFuncSetAttribute(gemm_h<3>, cudaFuncAttributeMaxDynamicSharedMemorySize, GEMM_SMEM);
    cudaFuncSetAttribute(attn_mma, cudaFuncAttributeMaxDynamicSharedMemorySize, ATT_SMEM_BYTES);

    // fused conversion (1 launch): hs + 4 weights + biases
    const int cv_total = CV_HS + 4 * CV_W + 768;
    conv_all<<<(cv_total + 255) / 256, 256>>>(
        (const float4*)hs,
        (const float4*)wq, (const float4*)wk, (const float4*)wv, (const float4*)wo,
        (const float4*)bq, (const float4*)bk, (const float4*)bv,
        (__half2*)hp, (__half2*)wqkvp, (__half2*)wop, (float4*)bqkvp);

    dim3 qkvgrid(3 * HID / TBN, MROWS / TBM);  // (24, 32)
    gemm_h<3><<<qkvgrid, 256, GEMM_SMEM>>>(hp, wqkvp, bqkvp, nullptr);

    dim3 agrid(SEQ / QT, NH, BATCH);           // (32, 16, 2)
    attn_mma<<<agrid, ATHR, ATT_SMEM_BYTES>>>();

    dim3 ogrid(HID / TBN, MROWS / TBM);        // (8, 32)
    gemm_h<0><<<ogrid, 256, GEMM_SMEM>>>(ap, wop, bo, out);
}